// round 1
// baseline (speedup 1.0000x reference)
#include <cuda_runtime.h>
#include <math.h>
#include <stdint.h>

// Problem constants
#define BB   2
#define TT   2048
#define CC   2048
#define NHH  16
#define DKK  128
#define LATT 512
#define DHRR 64
#define MROWS (BB * TT)   // 4096

// ---------------------------------------------------------------------------
// Scratch (static device globals -- no allocation allowed)
// ---------------------------------------------------------------------------
__device__ float g_h   [(size_t)MROWS * 1024];  // h = x@W_dkv + b      [4096,1024]
__device__ float g_kr  [(size_t)MROWS * 64];    // kR (post-rope)       [4096,64]
__device__ float g_qr  [(size_t)MROWS * 1024];  // qR (post-rope)       [4096,1024]
__device__ float g_kv  [(size_t)MROWS * 4096];  // [k | v]              [4096,4096]
__device__ float g_q   [(size_t)MROWS * 2048];  // q                    [4096,2048]
__device__ float g_attn[(size_t)MROWS * 2048];  // attention output     [4096,2048]

// ---------------------------------------------------------------------------
// Generic SGEMM: Y[M,N] = A[M,K](row stride lda, col offset aoff) @ W[K,N] + b
// BM=BN=64, BK=16, 256 threads, 4x4 microtile per thread.
// Requires M%64==0, N%64==0, K%16==0 (true for all calls here).
// ---------------------------------------------------------------------------
#define GBM 64
#define GBN 64
#define GBK 16

__global__ __launch_bounds__(256)
void sgemm_bias(const float* __restrict__ A, int lda, int aoff,
                const float* __restrict__ W,
                const float* __restrict__ bias,
                float* __restrict__ Y, int ldy,
                int M, int N, int K)
{
    __shared__ float As[GBK][GBM];
    __shared__ float Bs[GBK][GBN];

    const int tid = threadIdx.x;
    const int brow = blockIdx.y * GBM;
    const int bcol = blockIdx.x * GBN;
    const int tr = (tid / 16) * 4;   // 0..60
    const int tc = (tid % 16) * 4;   // 0..60

    float acc[4][4];
#pragma unroll
    for (int i = 0; i < 4; i++)
#pragma unroll
        for (int j = 0; j < 4; j++) acc[i][j] = 0.f;

    for (int k0 = 0; k0 < K; k0 += GBK) {
        // Load A tile (64 x 16), store transposed As[k][m]
#pragma unroll
        for (int it = 0; it < (GBM * GBK) / 256; it++) {
            int i = tid + it * 256;
            int m = i / GBK, kk = i % GBK;
            As[kk][m] = A[(size_t)(brow + m) * lda + aoff + k0 + kk];
        }
        // Load B tile (16 x 64)
#pragma unroll
        for (int it = 0; it < (GBK * GBN) / 256; it++) {
            int i = tid + it * 256;
            int kk = i / GBN, n = i % GBN;
            Bs[kk][n] = W[(size_t)(k0 + kk) * N + bcol + n];
        }
        __syncthreads();

#pragma unroll
        for (int kk = 0; kk < GBK; kk++) {
            float a[4], b[4];
#pragma unroll
            for (int i = 0; i < 4; i++) a[i] = As[kk][tr + i];
#pragma unroll
            for (int j = 0; j < 4; j++) b[j] = Bs[kk][tc + j];
#pragma unroll
            for (int i = 0; i < 4; i++)
#pragma unroll
                for (int j = 0; j < 4; j++) acc[i][j] = fmaf(a[i], b[j], acc[i][j]);
        }
        __syncthreads();
    }

#pragma unroll
    for (int i = 0; i < 4; i++)
#pragma unroll
        for (int j = 0; j < 4; j++)
            Y[(size_t)(brow + tr + i) * ldy + bcol + tc + j] =
                acc[i][j] + bias[bcol + tc + j];
}

// ---------------------------------------------------------------------------
// Interleaved RoPE, positions start at 1, theta = 10000^(-2*(pair)/c).
// Double-precision trig (angles can reach ~2048 rad; fast-math sinf would lose
// accuracy there).
// ---------------------------------------------------------------------------
__global__ void rope_kernel(float* __restrict__ buf, int rows, int c)
{
    const int pairs = c >> 1;
    const int idx = blockIdx.x * blockDim.x + threadIdx.x;
    if (idx >= rows * pairs) return;
    const int row = idx / pairs;
    const int i   = idx - row * pairs;
    const int t   = row & (TT - 1);   // row = b*T + t, T = 2048 (pow2)

    // match jax f32 tables: theta rounded to f32, angle = f32(freq * theta)
    float theta = (float)exp(-2.0 * (double)i / (double)c * log(10000.0));
    float angle = (float)(t + 1) * theta;
    double a = (double)angle;
    float cs = (float)cos(a);
    float sn = (float)sin(a);

    float* p = buf + (size_t)row * c + 2 * i;
    float x0 = p[0], x1 = p[1];
    p[0] = x0 * cs - x1 * sn;
    p[1] = x1 * cs + x0 * sn;
}

// ---------------------------------------------------------------------------
// Causal attention, one query row per block (128 threads).
//  q_full = [q(128) | qR(64)]  (192 dims), k_full = [k(128) | kR(64)]
//  scale = 1/sqrt(128). K tiles of 32 staged via shared memory (coalesced),
//  scores kept in shared (<= 2048), two-pass softmax, V accumulation with
//  one output dim per thread (coalesced V reads).
// ---------------------------------------------------------------------------
__global__ __launch_bounds__(128)
void attn_kernel(const float* __restrict__ q,
                 const float* __restrict__ qr,
                 const float* __restrict__ kv,
                 const float* __restrict__ kr,
                 float* __restrict__ out)
{
    const int bh = blockIdx.y;
    const int b  = bh / NHH;
    const int h  = bh % NHH;
    const int qi = blockIdx.x;
    const int row = b * TT + qi;
    const int tid = threadIdx.x;

    __shared__ float q_s[192];
    __shared__ float s_s[TT];
    __shared__ float k_s[32][196];
    __shared__ float red[33];

    if (tid < 128) q_s[tid]       = q [(size_t)row * CC + h * DKK + tid];
    if (tid < 64)  q_s[128 + tid] = qr[(size_t)row * (NHH * DHRR) + h * DHRR + tid];
    __syncthreads();

    const int nk = qi + 1;
    const size_t kbase = (size_t)(b * TT);
    const float scale = 0.08838834764831845f;   // 1/sqrt(128)

    // ---- scores ----
    for (int j0 = 0; j0 < nk; j0 += 32) {
        const int cnt = min(32, nk - j0);
        for (int idx = tid; idx < cnt * 192; idx += 128) {
            int jj = idx / 192, d = idx - jj * 192;
            float v;
            if (d < 128) v = kv[(kbase + j0 + jj) * 4096 + h * DKK + d];
            else         v = kr[(kbase + j0 + jj) * 64 + (d - 128)];
            k_s[jj][d] = v;
        }
        __syncthreads();

        const int g = tid >> 2;       // key within tile (4 lanes per key)
        const int l = tid & 3;
        float p = 0.f;
        if (g < cnt) {
#pragma unroll 8
            for (int d = l; d < 192; d += 4) p = fmaf(q_s[d], k_s[g][d], p);
        }
        p += __shfl_xor_sync(0xffffffffu, p, 1);
        p += __shfl_xor_sync(0xffffffffu, p, 2);
        if (l == 0 && g < cnt) s_s[j0 + g] = p * scale;
        __syncthreads();
    }

    // ---- softmax (two reductions in shared) ----
    float mx = -3.0e38f;
    for (int j = tid; j < nk; j += 128) mx = fmaxf(mx, s_s[j]);
#pragma unroll
    for (int o2 = 16; o2; o2 >>= 1) mx = fmaxf(mx, __shfl_xor_sync(0xffffffffu, mx, o2));
    if ((tid & 31) == 0) red[tid >> 5] = mx;
    __syncthreads();
    if (tid == 0) {
        float m = red[0];
        for (int w = 1; w < 4; w++) m = fmaxf(m, red[w]);
        red[32] = m;
    }
    __syncthreads();
    mx = red[32];

    float sum = 0.f;
    for (int j = tid; j < nk; j += 128) {
        float e = expf(s_s[j] - mx);
        s_s[j] = e;
        sum += e;
    }
#pragma unroll
    for (int o2 = 16; o2; o2 >>= 1) sum += __shfl_xor_sync(0xffffffffu, sum, o2);
    if ((tid & 31) == 0) red[tid >> 5] = sum;
    __syncthreads();
    if (tid == 0) red[32] = red[0] + red[1] + red[2] + red[3];
    __syncthreads();
    const float inv = 1.f / red[32];

    // ---- O = P @ V  (one output dim per thread, coalesced V reads) ----
    const float* vp = kv + kbase * 4096 + 2048 + h * DKK + tid;
    float a0 = 0.f, a1 = 0.f, a2 = 0.f, a3 = 0.f;
    int j = 0;
    for (; j + 4 <= nk; j += 4) {
        a0 = fmaf(s_s[j    ], vp[(size_t)(j    ) * 4096], a0);
        a1 = fmaf(s_s[j + 1], vp[(size_t)(j + 1) * 4096], a1);
        a2 = fmaf(s_s[j + 2], vp[(size_t)(j + 2) * 4096], a2);
        a3 = fmaf(s_s[j + 3], vp[(size_t)(j + 3) * 4096], a3);
    }
    for (; j < nk; j++) a0 = fmaf(s_s[j], vp[(size_t)j * 4096], a0);
    out[(size_t)row * CC + h * DKK + tid] = (a0 + a1 + a2 + a3) * inv;
}

// ---------------------------------------------------------------------------
// Host launcher
// ---------------------------------------------------------------------------
extern "C" void kernel_launch(void* const* d_in, const int* in_sizes, int n_in,
                              void* d_out, int out_size)
{
    (void)in_sizes; (void)n_in; (void)out_size;

    const float* x     = (const float*)d_in[0];
    const float* W_dkv = (const float*)d_in[1];
    const float* b_dkv = (const float*)d_in[2];
    const float* W_kr  = (const float*)d_in[3];
    const float* b_kr  = (const float*)d_in[4];
    const float* W_qr  = (const float*)d_in[5];
    const float* b_qr  = (const float*)d_in[6];
    const float* W_uv  = (const float*)d_in[7];
    const float* b_uv  = (const float*)d_in[8];
    const float* W_uq  = (const float*)d_in[9];
    const float* b_uq  = (const float*)d_in[10];
    const float* W_o   = (const float*)d_in[11];
    const float* b_o   = (const float*)d_in[12];
    float* out = (float*)d_out;

    float *h, *kr, *qr, *kvb, *qb, *attn;
    cudaGetSymbolAddress((void**)&h,    g_h);
    cudaGetSymbolAddress((void**)&kr,   g_kr);
    cudaGetSymbolAddress((void**)&qr,   g_qr);
    cudaGetSymbolAddress((void**)&kvb,  g_kv);
    cudaGetSymbolAddress((void**)&qb,   g_q);
    cudaGetSymbolAddress((void**)&attn, g_attn);

    const int M = MROWS;  // 4096

    // 1) h = x @ W_dkv + b_dkv            [4096,1024]
    sgemm_bias<<<dim3(1024 / GBN, M / GBM), 256>>>(x, CC, 0, W_dkv, b_dkv, h, 1024, M, 1024, CC);
    // 2) kr_lin = h @ W_kr + b_kr         [4096,64]
    sgemm_bias<<<dim3(64 / GBN, M / GBM), 256>>>(h, 1024, 0, W_kr, b_kr, kr, 64, M, 64, 1024);
    // 3) qr_lin = h @ W_qr + b_qr         [4096,1024]
    sgemm_bias<<<dim3(1024 / GBN, M / GBM), 256>>>(h, 1024, 0, W_qr, b_qr, qr, 1024, M, 1024, 1024);
    // 4) RoPE on both branches
    {
        int n1 = M * (64 / 2);
        rope_kernel<<<(n1 + 255) / 256, 256>>>(kr, M, 64);
        int n2 = M * (1024 / 2);
        rope_kernel<<<(n2 + 255) / 256, 256>>>(qr, M, 1024);
    }
    // 5) kv = cKV @ W_uv + b_uv           [4096,4096]  (cKV = h[:, :512])
    sgemm_bias<<<dim3(4096 / GBN, M / GBM), 256>>>(h, 1024, 0, W_uv, b_uv, kvb, 4096, M, 4096, LATT);
    // 6) q = cq @ W_uq + b_uq             [4096,2048]  (cq = h[:, 512:])
    sgemm_bias<<<dim3(2048 / GBN, M / GBM), 256>>>(h, 1024, LATT, W_uq, b_uq, qb, 2048, M, 2048, LATT);
    // 7) attention -> g_attn              [4096,2048]
    attn_kernel<<<dim3(TT, BB * NHH), 128>>>(qb, qr, kvb, kr, attn);
    // 8) out = attn @ W_o + b_o           [4096,2048]
    sgemm_bias<<<dim3(2048 / GBN, M / GBM), 256>>>(attn, 2048, 0, W_o, b_o, out, 2048, M, 2048, 2048);
}

// round 2
// speedup vs baseline: 8.2460x; 8.2460x over previous
#include <cuda_runtime.h>
#include <math.h>
#include <stdint.h>

// Problem constants
#define BB   2
#define TT   2048
#define CC   2048
#define NHH  16
#define DKK  128
#define LATT 512
#define DHRR 64
#define MROWS (BB * TT)   // 4096

// ---------------------------------------------------------------------------
// Scratch (static device globals -- no allocation allowed)
// ---------------------------------------------------------------------------
__device__ float g_h   [(size_t)MROWS * 1024];  // h = x@W_dkv + b      [4096,1024]
__device__ float g_kr  [(size_t)MROWS * 64];    // kR (post-rope)       [4096,64]
__device__ float g_qr  [(size_t)MROWS * 1024];  // qR (post-rope)       [4096,1024]
__device__ float g_kv  [(size_t)MROWS * 4096];  // [k | v]              [4096,4096]
__device__ float g_q   [(size_t)MROWS * 2048];  // q                    [4096,2048]
__device__ float g_attn[(size_t)MROWS * 2048];  // attention output     [4096,2048]

// ---------------------------------------------------------------------------
// Fast SGEMM: Y[M,N] = A[M,K](lda, col offset aoff) @ W[K,N] + bias
// 128x128 tile, BK=8, 256 threads, 8x8 microtile, float4 everywhere,
// register prefetch of next k-tile. Requires M%128==0, N%128==0, K%8==0.
// ---------------------------------------------------------------------------
__global__ __launch_bounds__(256)
void sgemm128(const float* __restrict__ A, int lda, int aoff,
              const float* __restrict__ W,
              const float* __restrict__ bias,
              float* __restrict__ Y, int ldy,
              int N, int K)
{
    __shared__ float As[8][132];
    __shared__ float Bs[8][128];

    const int tid = threadIdx.x;
    const int brow = blockIdx.y * 128;
    const int bcol = blockIdx.x * 128;
    const int arow = tid >> 1, acol = (tid & 1) * 4;
    const int bkr  = tid >> 5, bcol4 = (tid & 31) * 4;
    const int ty = tid >> 4, tx = tid & 15;

    const float* Aptr = A + (size_t)(brow + arow) * lda + aoff + acol;
    const float* Wptr = W + (size_t)bkr * N + bcol + bcol4;

    float4 pa = *(const float4*)Aptr;
    float4 pb = *(const float4*)Wptr;

    float acc[8][8];
#pragma unroll
    for (int i = 0; i < 8; i++)
#pragma unroll
        for (int j = 0; j < 8; j++) acc[i][j] = 0.f;

    for (int k0 = 0; k0 < K; k0 += 8) {
        As[acol + 0][arow] = pa.x;
        As[acol + 1][arow] = pa.y;
        As[acol + 2][arow] = pa.z;
        As[acol + 3][arow] = pa.w;
        *(float4*)&Bs[bkr][bcol4] = pb;
        __syncthreads();
        if (k0 + 8 < K) {
            pa = *(const float4*)(Aptr + k0 + 8);
            pb = *(const float4*)(Wptr + (size_t)(k0 + 8) * N);
        }
#pragma unroll
        for (int kk = 0; kk < 8; kk++) {
            float4 a0 = *(float4*)&As[kk][ty * 4];
            float4 a1 = *(float4*)&As[kk][64 + ty * 4];
            float4 b0 = *(float4*)&Bs[kk][tx * 4];
            float4 b1 = *(float4*)&Bs[kk][64 + tx * 4];
            float av[8] = {a0.x, a0.y, a0.z, a0.w, a1.x, a1.y, a1.z, a1.w};
            float bv[8] = {b0.x, b0.y, b0.z, b0.w, b1.x, b1.y, b1.z, b1.w};
#pragma unroll
            for (int i = 0; i < 8; i++)
#pragma unroll
                for (int j = 0; j < 8; j++)
                    acc[i][j] = fmaf(av[i], bv[j], acc[i][j]);
        }
        __syncthreads();
    }

#pragma unroll
    for (int i = 0; i < 8; i++) {
        int r = brow + ((i < 4) ? (ty * 4 + i) : (64 + ty * 4 + i - 4));
        float* yrow = Y + (size_t)r * ldy + bcol;
        float4 o0, o1;
        o0.x = acc[i][0] + bias[bcol + tx * 4 + 0];
        o0.y = acc[i][1] + bias[bcol + tx * 4 + 1];
        o0.z = acc[i][2] + bias[bcol + tx * 4 + 2];
        o0.w = acc[i][3] + bias[bcol + tx * 4 + 3];
        o1.x = acc[i][4] + bias[bcol + 64 + tx * 4 + 0];
        o1.y = acc[i][5] + bias[bcol + 64 + tx * 4 + 1];
        o1.z = acc[i][6] + bias[bcol + 64 + tx * 4 + 2];
        o1.w = acc[i][7] + bias[bcol + 64 + tx * 4 + 3];
        *(float4*)&yrow[tx * 4]      = o0;
        *(float4*)&yrow[64 + tx * 4] = o1;
    }
}

// ---------------------------------------------------------------------------
// Small SGEMM (kept for the N=64 W_kr projection only)
// ---------------------------------------------------------------------------
#define GBM 64
#define GBN 64
#define GBK 16

__global__ __launch_bounds__(256)
void sgemm_bias(const float* __restrict__ A, int lda, int aoff,
                const float* __restrict__ W,
                const float* __restrict__ bias,
                float* __restrict__ Y, int ldy,
                int M, int N, int K)
{
    __shared__ float As[GBK][GBM];
    __shared__ float Bs[GBK][GBN];

    const int tid = threadIdx.x;
    const int brow = blockIdx.y * GBM;
    const int bcol = blockIdx.x * GBN;
    const int tr = (tid / 16) * 4;
    const int tc = (tid % 16) * 4;

    float acc[4][4];
#pragma unroll
    for (int i = 0; i < 4; i++)
#pragma unroll
        for (int j = 0; j < 4; j++) acc[i][j] = 0.f;

    for (int k0 = 0; k0 < K; k0 += GBK) {
#pragma unroll
        for (int it = 0; it < (GBM * GBK) / 256; it++) {
            int i = tid + it * 256;
            int m = i / GBK, kk = i % GBK;
            As[kk][m] = A[(size_t)(brow + m) * lda + aoff + k0 + kk];
        }
#pragma unroll
        for (int it = 0; it < (GBK * GBN) / 256; it++) {
            int i = tid + it * 256;
            int kk = i / GBN, n = i % GBN;
            Bs[kk][n] = W[(size_t)(k0 + kk) * N + bcol + n];
        }
        __syncthreads();

#pragma unroll
        for (int kk = 0; kk < GBK; kk++) {
            float a[4], b[4];
#pragma unroll
            for (int i = 0; i < 4; i++) a[i] = As[kk][tr + i];
#pragma unroll
            for (int j = 0; j < 4; j++) b[j] = Bs[kk][tc + j];
#pragma unroll
            for (int i = 0; i < 4; i++)
#pragma unroll
                for (int j = 0; j < 4; j++) acc[i][j] = fmaf(a[i], b[j], acc[i][j]);
        }
        __syncthreads();
    }

#pragma unroll
    for (int i = 0; i < 4; i++)
#pragma unroll
        for (int j = 0; j < 4; j++)
            Y[(size_t)(brow + tr + i) * ldy + bcol + tc + j] =
                acc[i][j] + bias[bcol + tc + j];
}

// ---------------------------------------------------------------------------
// Interleaved RoPE (double-precision trig; angles up to ~2048 rad)
// ---------------------------------------------------------------------------
__global__ void rope_kernel(float* __restrict__ buf, int rows, int c)
{
    const int pairs = c >> 1;
    const int idx = blockIdx.x * blockDim.x + threadIdx.x;
    if (idx >= rows * pairs) return;
    const int row = idx / pairs;
    const int i   = idx - row * pairs;
    const int t   = row & (TT - 1);

    float theta = (float)exp(-2.0 * (double)i / (double)c * log(10000.0));
    float angle = (float)(t + 1) * theta;
    double a = (double)angle;
    float cs = (float)cos(a);
    float sn = (float)sin(a);

    float* p = buf + (size_t)row * c + 2 * i;
    float x0 = p[0], x1 = p[1];
    p[0] = x0 * cs - x1 * sn;
    p[1] = x1 * cs + x0 * sn;
}

// ---------------------------------------------------------------------------
// Flash attention: 64 queries x 64 keys per tile, 256 threads.
// Score microtile 4x4 (rows ty+16i, cols tx+16j), output microtile 4x8.
// Online softmax; P staged via smem. ~147KB dynamic smem.
// ---------------------------------------------------------------------------
__global__ __launch_bounds__(256)
void attn_flash(const float* __restrict__ q, const float* __restrict__ qr,
                const float* __restrict__ kv, const float* __restrict__ kr,
                float* __restrict__ out)
{
    extern __shared__ float sm[];
    float* Qs = sm;                  // [64][196]
    float* Ks = Qs + 64 * 196;       // [64][196]
    float* Vs = Ks + 64 * 196;       // [64][128]
    float* Ps = Vs + 64 * 128;       // [64][68]

    const int bh = blockIdx.y;
    const int b = bh >> 4, h = bh & 15;
    const int qb = gridDim.x - 1 - blockIdx.x;   // largest blocks first
    const int tid = threadIdx.x;
    const int ty = tid >> 4, tx = tid & 15;
    const int row0 = b * TT + qb * 64;
    const size_t kbase = (size_t)b * TT;
    const float scale = 0.08838834764831845f;    // 1/sqrt(128)

    // load Q tile [64 x 192], pre-scaled
    for (int idx = tid; idx < 64 * 48; idx += 256) {
        int qi = idx / 48, d4 = (idx % 48) * 4;
        float4 v;
        if (d4 < 128)
            v = *(const float4*)&q[(size_t)(row0 + qi) * 2048 + h * 128 + d4];
        else
            v = *(const float4*)&qr[(size_t)(row0 + qi) * 1024 + h * 64 + (d4 - 128)];
        v.x *= scale; v.y *= scale; v.z *= scale; v.w *= scale;
        *(float4*)&Qs[qi * 196 + d4] = v;
    }

    float m[4], l[4], acc[4][8];
#pragma unroll
    for (int i = 0; i < 4; i++) {
        m[i] = -3.0e38f; l[i] = 0.f;
#pragma unroll
        for (int j = 0; j < 8; j++) acc[i][j] = 0.f;
    }

    const int ntiles = qb + 1;
    for (int t = 0; t < ntiles; t++) {
        const int j0 = t * 64;
        __syncthreads();
        // load K tile [64 x 192] and V tile [64 x 128]
        for (int idx = tid; idx < 64 * 48; idx += 256) {
            int j = idx / 48, d4 = (idx % 48) * 4;
            float4 v;
            if (d4 < 128)
                v = *(const float4*)&kv[(kbase + j0 + j) * 4096 + h * 128 + d4];
            else
                v = *(const float4*)&kr[(kbase + j0 + j) * 64 + (d4 - 128)];
            *(float4*)&Ks[j * 196 + d4] = v;
        }
        for (int idx = tid; idx < 64 * 32; idx += 256) {
            int j = idx / 32, d4 = (idx % 32) * 4;
            *(float4*)&Vs[j * 128 + d4] =
                *(const float4*)&kv[(kbase + j0 + j) * 4096 + 2048 + h * 128 + d4];
        }
        __syncthreads();

        // S = Q @ K^T (4x4 microtile)
        float s[4][4];
#pragma unroll
        for (int i = 0; i < 4; i++)
#pragma unroll
            for (int j = 0; j < 4; j++) s[i][j] = 0.f;

        for (int d4 = 0; d4 < 192; d4 += 4) {
            float4 qv[4], kk[4];
#pragma unroll
            for (int i = 0; i < 4; i++) qv[i] = *(float4*)&Qs[(ty + 16 * i) * 196 + d4];
#pragma unroll
            for (int j = 0; j < 4; j++) kk[j] = *(float4*)&Ks[(tx + 16 * j) * 196 + d4];
#pragma unroll
            for (int i = 0; i < 4; i++)
#pragma unroll
                for (int j = 0; j < 4; j++) {
                    s[i][j] = fmaf(qv[i].x, kk[j].x, s[i][j]);
                    s[i][j] = fmaf(qv[i].y, kk[j].y, s[i][j]);
                    s[i][j] = fmaf(qv[i].z, kk[j].z, s[i][j]);
                    s[i][j] = fmaf(qv[i].w, kk[j].w, s[i][j]);
                }
        }

        // causal mask (diagonal tile only)
        if (t == ntiles - 1) {
#pragma unroll
            for (int i = 0; i < 4; i++) {
                int qrow = qb * 64 + ty + 16 * i;
#pragma unroll
                for (int j = 0; j < 4; j++)
                    if (j0 + tx + 16 * j > qrow) s[i][j] = -1.0e30f;
            }
        }

        // online softmax update
#pragma unroll
        for (int i = 0; i < 4; i++) {
            float mr = fmaxf(fmaxf(s[i][0], s[i][1]), fmaxf(s[i][2], s[i][3]));
#pragma unroll
            for (int o = 1; o < 16; o <<= 1)
                mr = fmaxf(mr, __shfl_xor_sync(0xffffffffu, mr, o));
            float mn = fmaxf(m[i], mr);
            float alpha = __expf(m[i] - mn);
            m[i] = mn;
            float rs = 0.f;
#pragma unroll
            for (int j = 0; j < 4; j++) {
                float p = __expf(s[i][j] - mn);
                s[i][j] = p;
                rs += p;
            }
#pragma unroll
            for (int o = 1; o < 16; o <<= 1)
                rs += __shfl_xor_sync(0xffffffffu, rs, o);
            l[i] = l[i] * alpha + rs;
#pragma unroll
            for (int j = 0; j < 8; j++) acc[i][j] *= alpha;
#pragma unroll
            for (int j = 0; j < 4; j++)
                Ps[(ty + 16 * i) * 68 + tx + 16 * j] = s[i][j];
        }
        __syncthreads();

        // O += P @ V (4x8 microtile, rows match score rows)
#pragma unroll 2
        for (int j = 0; j < 64; j++) {
            float pj[4];
#pragma unroll
            for (int i = 0; i < 4; i++) pj[i] = Ps[(ty + 16 * i) * 68 + j];
#pragma unroll
            for (int c = 0; c < 8; c++) {
                float vv = Vs[j * 128 + tx + 16 * c];
#pragma unroll
                for (int i = 0; i < 4; i++) acc[i][c] = fmaf(pj[i], vv, acc[i][c]);
            }
        }
    }

    // write normalized output
#pragma unroll
    for (int i = 0; i < 4; i++) {
        float inv = 1.f / l[i];
        int orow = row0 + ty + 16 * i;
#pragma unroll
        for (int c = 0; c < 8; c++)
            out[(size_t)orow * 2048 + h * 128 + tx + 16 * c] = acc[i][c] * inv;
    }
}

// ---------------------------------------------------------------------------
// Host launcher
// ---------------------------------------------------------------------------
extern "C" void kernel_launch(void* const* d_in, const int* in_sizes, int n_in,
                              void* d_out, int out_size)
{
    (void)in_sizes; (void)n_in; (void)out_size;

    const float* x     = (const float*)d_in[0];
    const float* W_dkv = (const float*)d_in[1];
    const float* b_dkv = (const float*)d_in[2];
    const float* W_kr  = (const float*)d_in[3];
    const float* b_kr  = (const float*)d_in[4];
    const float* W_qr  = (const float*)d_in[5];
    const float* b_qr  = (const float*)d_in[6];
    const float* W_uv  = (const float*)d_in[7];
    const float* b_uv  = (const float*)d_in[8];
    const float* W_uq  = (const float*)d_in[9];
    const float* b_uq  = (const float*)d_in[10];
    const float* W_o   = (const float*)d_in[11];
    const float* b_o   = (const float*)d_in[12];
    float* out = (float*)d_out;

    float *h, *kr, *qr, *kvb, *qb, *attn;
    cudaGetSymbolAddress((void**)&h,    g_h);
    cudaGetSymbolAddress((void**)&kr,   g_kr);
    cudaGetSymbolAddress((void**)&qr,   g_qr);
    cudaGetSymbolAddress((void**)&kvb,  g_kv);
    cudaGetSymbolAddress((void**)&qb,   g_q);
    cudaGetSymbolAddress((void**)&attn, g_attn);

    const int M = MROWS;  // 4096

    // 1) h = x @ W_dkv + b_dkv            [4096,1024]
    sgemm128<<<dim3(1024 / 128, M / 128), 256>>>(x, CC, 0, W_dkv, b_dkv, h, 1024, 1024, CC);
    // 2) kr_lin = h @ W_kr + b_kr         [4096,64]
    sgemm_bias<<<dim3(64 / GBN, M / GBM), 256>>>(h, 1024, 0, W_kr, b_kr, kr, 64, M, 64, 1024);
    // 3) qr_lin = h @ W_qr + b_qr         [4096,1024]
    sgemm128<<<dim3(1024 / 128, M / 128), 256>>>(h, 1024, 0, W_qr, b_qr, qr, 1024, 1024, 1024);
    // 4) RoPE on both branches
    {
        int n1 = M * (64 / 2);
        rope_kernel<<<(n1 + 255) / 256, 256>>>(kr, M, 64);
        int n2 = M * (1024 / 2);
        rope_kernel<<<(n2 + 255) / 256, 256>>>(qr, M, 1024);
    }
    // 5) kv = cKV @ W_uv + b_uv           [4096,4096]
    sgemm128<<<dim3(4096 / 128, M / 128), 256>>>(h, 1024, 0, W_uv, b_uv, kvb, 4096, 4096, LATT);
    // 6) q = cq @ W_uq + b_uq             [4096,2048]
    sgemm128<<<dim3(2048 / 128, M / 128), 256>>>(h, 1024, LATT, W_uq, b_uq, qb, 2048, 2048, LATT);
    // 7) attention -> g_attn
    {
        size_t smem = (size_t)(64 * 196 + 64 * 196 + 64 * 128 + 64 * 68) * sizeof(float);
        cudaFuncSetAttribute(attn_flash, cudaFuncAttributeMaxDynamicSharedMemorySize, (int)smem);
        attn_flash<<<dim3(TT / 64, BB * NHH), 256, smem>>>(qb, qr, kvb, kr, attn);
    }
    // 8) out = attn @ W_o + b_o           [4096,2048]
    sgemm128<<<dim3(2048 / 128, M / 128), 256>>>(attn, 2048, 0, W_o, b_o, out, 2048, 2048, 2048);
}

// round 3
// speedup vs baseline: 8.8304x; 1.0709x over previous
#include <cuda_runtime.h>
#include <cuda_bf16.h>
#include <math.h>
#include <stdint.h>

// Problem constants
#define BB   2
#define TT   2048
#define CC   2048
#define NHH  16
#define DKK  128
#define LATT 512
#define DHRR 64
#define MROWS (BB * TT)   // 4096

// ---------------------------------------------------------------------------
// Scratch (static device globals -- no allocation allowed)
// ---------------------------------------------------------------------------
__device__ float g_h   [(size_t)MROWS * 1024];
__device__ float g_kr  [(size_t)MROWS * 64];
__device__ float g_qr  [(size_t)MROWS * 1024];
__device__ float g_kv  [(size_t)MROWS * 4096];
__device__ float g_q   [(size_t)MROWS * 2048];
__device__ float g_attn[(size_t)MROWS * 2048];

// ---------------------------------------------------------------------------
// 3xBF16 tensor-core GEMM: Y[M,N] = A[M,K](lda, col off aoff) @ W[K,N] + bias
// fp32 in/out; internally A,W split into bf16 hi+lo; acc = Ahi*Bhi + Ahi*Blo
// + Alo*Bhi in fp32 (mma.m16n8k16). Requires M%128==0, N%128==0, K%32==0.
// 128x128x32 tile, 256 threads, warp grid 2(m) x 4(n), 64x32 per warp.
// ---------------------------------------------------------------------------
#define KPAD 34   // bf16 stride per row: 32 + 2 pad -> 17 words, conflict-free

__device__ __forceinline__ void mma_bf16(float* d, const uint32_t* a, const uint32_t* b)
{
    asm volatile(
        "mma.sync.aligned.m16n8k16.row.col.f32.bf16.bf16.f32 "
        "{%0,%1,%2,%3}, {%4,%5,%6,%7}, {%8,%9}, {%0,%1,%2,%3};\n"
        : "+f"(d[0]), "+f"(d[1]), "+f"(d[2]), "+f"(d[3])
        : "r"(a[0]), "r"(a[1]), "r"(a[2]), "r"(a[3]), "r"(b[0]), "r"(b[1]));
}

__device__ __forceinline__ void split_bf16(float x, __nv_bfloat16& hi, __nv_bfloat16& lo)
{
    hi = __float2bfloat16(x);
    lo = __float2bfloat16(x - __bfloat162float(hi));
}

__global__ __launch_bounds__(256, 1)
void gemm_bf16x3(const float* __restrict__ A, int lda, int aoff,
                 const float* __restrict__ W,
                 const float* __restrict__ bias,
                 float* __restrict__ Y, int ldy,
                 int N, int K)
{
    __shared__ __nv_bfloat16 Ahi[128 * KPAD], Alo[128 * KPAD];
    __shared__ __nv_bfloat16 Bhi[128 * KPAD], Blo[128 * KPAD];   // N-major!

    const int tid = threadIdx.x, lane = tid & 31, wid = tid >> 5;
    const int brow = blockIdx.y * 128, bcol = blockIdx.x * 128;
    const int wm = (wid >> 2) * 64, wn = (wid & 3) * 32;

    // A gmem tile [128 x 32]: thread loads rows ra, ra+64; cols ca..ca+7
    const int ra = tid >> 2, ca = (tid & 3) * 8;
    const float* Ap = A + (size_t)(brow + ra) * lda + aoff + ca;
    // B gmem tile [32 x 128]: thread loads row kb; cols nb..nb+15
    const int kb = tid >> 3, nb = (tid & 7) * 16;
    const float* Wp = W + (size_t)kb * N + bcol + nb;

    float4 pa0 = *(const float4*)(Ap);
    float4 pa1 = *(const float4*)(Ap + 4);
    float4 pa2 = *(const float4*)(Ap + (size_t)64 * lda);
    float4 pa3 = *(const float4*)(Ap + (size_t)64 * lda + 4);
    float4 pb0 = *(const float4*)(Wp);
    float4 pb1 = *(const float4*)(Wp + 4);
    float4 pb2 = *(const float4*)(Wp + 8);
    float4 pb3 = *(const float4*)(Wp + 12);

    float acc[4][4][4];
#pragma unroll
    for (int i = 0; i < 4; i++)
#pragma unroll
        for (int j = 0; j < 4; j++)
#pragma unroll
            for (int f = 0; f < 4; f++) acc[i][j][f] = 0.f;

    for (int k0 = 0; k0 < K; k0 += 32) {
        // --- convert + store A (row-major, K contiguous) ---
        {
            float av[8] = {pa0.x, pa0.y, pa0.z, pa0.w, pa1.x, pa1.y, pa1.z, pa1.w};
            float aw[8] = {pa2.x, pa2.y, pa2.z, pa2.w, pa3.x, pa3.y, pa3.z, pa3.w};
#pragma unroll
            for (int e = 0; e < 8; e++) {
                __nv_bfloat16 h, l;
                split_bf16(av[e], h, l);
                Ahi[ra * KPAD + ca + e] = h;  Alo[ra * KPAD + ca + e] = l;
                split_bf16(aw[e], h, l);
                Ahi[(ra + 64) * KPAD + ca + e] = h;  Alo[(ra + 64) * KPAD + ca + e] = l;
            }
        }
        // --- convert + store B transposed (N-major, K contiguous) ---
        {
            float bv[16] = {pb0.x, pb0.y, pb0.z, pb0.w, pb1.x, pb1.y, pb1.z, pb1.w,
                            pb2.x, pb2.y, pb2.z, pb2.w, pb3.x, pb3.y, pb3.z, pb3.w};
#pragma unroll
            for (int j = 0; j < 16; j++) {
                __nv_bfloat16 h, l;
                split_bf16(bv[j], h, l);
                Bhi[(nb + j) * KPAD + kb] = h;  Blo[(nb + j) * KPAD + kb] = l;
            }
        }
        __syncthreads();

        // --- prefetch next k-tile ---
        if (k0 + 32 < K) {
            pa0 = *(const float4*)(Ap + k0 + 32);
            pa1 = *(const float4*)(Ap + k0 + 36);
            pa2 = *(const float4*)(Ap + (size_t)64 * lda + k0 + 32);
            pa3 = *(const float4*)(Ap + (size_t)64 * lda + k0 + 36);
            const float* Wn = Wp + (size_t)(k0 + 32) * N;
            pb0 = *(const float4*)(Wn);
            pb1 = *(const float4*)(Wn + 4);
            pb2 = *(const float4*)(Wn + 8);
            pb3 = *(const float4*)(Wn + 12);
        }

        // --- compute 2 x k16 ---
#pragma unroll
        for (int kk = 0; kk < 32; kk += 16) {
            uint32_t ah[4][4], al[4][4], bh[4][2], bl[4][2];
            const int arow = lane >> 2;
            const int acol = (lane & 3) * 2 + kk;
#pragma unroll
            for (int i = 0; i < 4; i++) {
                int r0 = (wm + i * 16 + arow) * KPAD;
                ah[i][0] = *(const uint32_t*)&Ahi[r0 + acol];
                ah[i][1] = *(const uint32_t*)&Ahi[r0 + 8 * KPAD + acol];
                ah[i][2] = *(const uint32_t*)&Ahi[r0 + acol + 8];
                ah[i][3] = *(const uint32_t*)&Ahi[r0 + 8 * KPAD + acol + 8];
                al[i][0] = *(const uint32_t*)&Alo[r0 + acol];
                al[i][1] = *(const uint32_t*)&Alo[r0 + 8 * KPAD + acol];
                al[i][2] = *(const uint32_t*)&Alo[r0 + acol + 8];
                al[i][3] = *(const uint32_t*)&Alo[r0 + 8 * KPAD + acol + 8];
            }
#pragma unroll
            for (int j = 0; j < 4; j++) {
                int n0 = (wn + j * 8 + arow) * KPAD;
                bh[j][0] = *(const uint32_t*)&Bhi[n0 + acol];
                bh[j][1] = *(const uint32_t*)&Bhi[n0 + acol + 8];
                bl[j][0] = *(const uint32_t*)&Blo[n0 + acol];
                bl[j][1] = *(const uint32_t*)&Blo[n0 + acol + 8];
            }
#pragma unroll
            for (int i = 0; i < 4; i++)
#pragma unroll
                for (int j = 0; j < 4; j++) {
                    mma_bf16(acc[i][j], ah[i], bh[j]);
                    mma_bf16(acc[i][j], ah[i], bl[j]);
                    mma_bf16(acc[i][j], al[i], bh[j]);
                }
        }
        __syncthreads();
    }

    // --- epilogue: bias + fp32 store ---
#pragma unroll
    for (int i = 0; i < 4; i++) {
#pragma unroll
        for (int j = 0; j < 4; j++) {
            int r0 = brow + wm + i * 16 + (lane >> 2);
            int c0 = bcol + wn + j * 8 + (lane & 3) * 2;
            float b0 = bias[c0], b1 = bias[c0 + 1];
            float2 v0 = {acc[i][j][0] + b0, acc[i][j][1] + b1};
            float2 v1 = {acc[i][j][2] + b0, acc[i][j][3] + b1};
            *(float2*)&Y[(size_t)r0 * ldy + c0] = v0;
            *(float2*)&Y[(size_t)(r0 + 8) * ldy + c0] = v1;
        }
    }
}

// ---------------------------------------------------------------------------
// Small SGEMM (kept for the N=64 W_kr projection only)
// ---------------------------------------------------------------------------
#define GBM 64
#define GBN 64
#define GBK 16

__global__ __launch_bounds__(256)
void sgemm_bias(const float* __restrict__ A, int lda, int aoff,
                const float* __restrict__ W,
                const float* __restrict__ bias,
                float* __restrict__ Y, int ldy,
                int M, int N, int K)
{
    __shared__ float As[GBK][GBM];
    __shared__ float Bs[GBK][GBN];

    const int tid = threadIdx.x;
    const int brow = blockIdx.y * GBM;
    const int bcol = blockIdx.x * GBN;
    const int tr = (tid / 16) * 4;
    const int tc = (tid % 16) * 4;

    float acc[4][4];
#pragma unroll
    for (int i = 0; i < 4; i++)
#pragma unroll
        for (int j = 0; j < 4; j++) acc[i][j] = 0.f;

    for (int k0 = 0; k0 < K; k0 += GBK) {
#pragma unroll
        for (int it = 0; it < (GBM * GBK) / 256; it++) {
            int i = tid + it * 256;
            int m = i / GBK, kk = i % GBK;
            As[kk][m] = A[(size_t)(brow + m) * lda + aoff + k0 + kk];
        }
#pragma unroll
        for (int it = 0; it < (GBK * GBN) / 256; it++) {
            int i = tid + it * 256;
            int kk = i / GBN, n = i % GBN;
            Bs[kk][n] = W[(size_t)(k0 + kk) * N + bcol + n];
        }
        __syncthreads();

#pragma unroll
        for (int kk = 0; kk < GBK; kk++) {
            float a[4], b[4];
#pragma unroll
            for (int i = 0; i < 4; i++) a[i] = As[kk][tr + i];
#pragma unroll
            for (int j = 0; j < 4; j++) b[j] = Bs[kk][tc + j];
#pragma unroll
            for (int i = 0; i < 4; i++)
#pragma unroll
                for (int j = 0; j < 4; j++) acc[i][j] = fmaf(a[i], b[j], acc[i][j]);
        }
        __syncthreads();
    }

#pragma unroll
    for (int i = 0; i < 4; i++)
#pragma unroll
        for (int j = 0; j < 4; j++)
            Y[(size_t)(brow + tr + i) * ldy + bcol + tc + j] =
                acc[i][j] + bias[bcol + tc + j];
}

// ---------------------------------------------------------------------------
// Interleaved RoPE (double-precision trig; angles up to ~2048 rad)
// ---------------------------------------------------------------------------
__global__ void rope_kernel(float* __restrict__ buf, int rows, int c)
{
    const int pairs = c >> 1;
    const int idx = blockIdx.x * blockDim.x + threadIdx.x;
    if (idx >= rows * pairs) return;
    const int row = idx / pairs;
    const int i   = idx - row * pairs;
    const int t   = row & (TT - 1);

    float theta = (float)exp(-2.0 * (double)i / (double)c * log(10000.0));
    float angle = (float)(t + 1) * theta;
    double a = (double)angle;
    float cs = (float)cos(a);
    float sn = (float)sin(a);

    float* p = buf + (size_t)row * c + 2 * i;
    float x0 = p[0], x1 = p[1];
    p[0] = x0 * cs - x1 * sn;
    p[1] = x1 * cs + x0 * sn;
}

// ---------------------------------------------------------------------------
// Flash attention: 64 queries x 64 keys per tile, 256 threads.
// ---------------------------------------------------------------------------
__global__ __launch_bounds__(256)
void attn_flash(const float* __restrict__ q, const float* __restrict__ qr,
                const float* __restrict__ kv, const float* __restrict__ kr,
                float* __restrict__ out)
{
    extern __shared__ float sm[];
    float* Qs = sm;                  // [64][196]
    float* Ks = Qs + 64 * 196;       // [64][196]
    float* Vs = Ks + 64 * 196;       // [64][128]
    float* Ps = Vs + 64 * 128;       // [64][68]

    const int bh = blockIdx.y;
    const int b = bh >> 4, h = bh & 15;
    const int qb = gridDim.x - 1 - blockIdx.x;   // largest blocks first
    const int tid = threadIdx.x;
    const int ty = tid >> 4, tx = tid & 15;
    const int row0 = b * TT + qb * 64;
    const size_t kbase = (size_t)b * TT;
    const float scale = 0.08838834764831845f;    // 1/sqrt(128)

    for (int idx = tid; idx < 64 * 48; idx += 256) {
        int qi = idx / 48, d4 = (idx % 48) * 4;
        float4 v;
        if (d4 < 128)
            v = *(const float4*)&q[(size_t)(row0 + qi) * 2048 + h * 128 + d4];
        else
            v = *(const float4*)&qr[(size_t)(row0 + qi) * 1024 + h * 64 + (d4 - 128)];
        v.x *= scale; v.y *= scale; v.z *= scale; v.w *= scale;
        *(float4*)&Qs[qi * 196 + d4] = v;
    }

    float m[4], l[4], acc[4][8];
#pragma unroll
    for (int i = 0; i < 4; i++) {
        m[i] = -3.0e38f; l[i] = 0.f;
#pragma unroll
        for (int j = 0; j < 8; j++) acc[i][j] = 0.f;
    }

    const int ntiles = qb + 1;
    for (int t = 0; t < ntiles; t++) {
        const int j0 = t * 64;
        __syncthreads();
        for (int idx = tid; idx < 64 * 48; idx += 256) {
            int j = idx / 48, d4 = (idx % 48) * 4;
            float4 v;
            if (d4 < 128)
                v = *(const float4*)&kv[(kbase + j0 + j) * 4096 + h * 128 + d4];
            else
                v = *(const float4*)&kr[(kbase + j0 + j) * 64 + (d4 - 128)];
            *(float4*)&Ks[j * 196 + d4] = v;
        }
        for (int idx = tid; idx < 64 * 32; idx += 256) {
            int j = idx / 32, d4 = (idx % 32) * 4;
            *(float4*)&Vs[j * 128 + d4] =
                *(const float4*)&kv[(kbase + j0 + j) * 4096 + 2048 + h * 128 + d4];
        }
        __syncthreads();

        float s[4][4];
#pragma unroll
        for (int i = 0; i < 4; i++)
#pragma unroll
            for (int j = 0; j < 4; j++) s[i][j] = 0.f;

        for (int d4 = 0; d4 < 192; d4 += 4) {
            float4 qv[4], kk[4];
#pragma unroll
            for (int i = 0; i < 4; i++) qv[i] = *(float4*)&Qs[(ty + 16 * i) * 196 + d4];
#pragma unroll
            for (int j = 0; j < 4; j++) kk[j] = *(float4*)&Ks[(tx + 16 * j) * 196 + d4];
#pragma unroll
            for (int i = 0; i < 4; i++)
#pragma unroll
                for (int j = 0; j < 4; j++) {
                    s[i][j] = fmaf(qv[i].x, kk[j].x, s[i][j]);
                    s[i][j] = fmaf(qv[i].y, kk[j].y, s[i][j]);
                    s[i][j] = fmaf(qv[i].z, kk[j].z, s[i][j]);
                    s[i][j] = fmaf(qv[i].w, kk[j].w, s[i][j]);
                }
        }

        if (t == ntiles - 1) {
#pragma unroll
            for (int i = 0; i < 4; i++) {
                int qrow = qb * 64 + ty + 16 * i;
#pragma unroll
                for (int j = 0; j < 4; j++)
                    if (j0 + tx + 16 * j > qrow) s[i][j] = -1.0e30f;
            }
        }

#pragma unroll
        for (int i = 0; i < 4; i++) {
            float mr = fmaxf(fmaxf(s[i][0], s[i][1]), fmaxf(s[i][2], s[i][3]));
#pragma unroll
            for (int o = 1; o < 16; o <<= 1)
                mr = fmaxf(mr, __shfl_xor_sync(0xffffffffu, mr, o));
            float mn = fmaxf(m[i], mr);
            float alpha = __expf(m[i] - mn);
            m[i] = mn;
            float rs = 0.f;
#pragma unroll
            for (int j = 0; j < 4; j++) {
                float p = __expf(s[i][j] - mn);
                s[i][j] = p;
                rs += p;
            }
#pragma unroll
            for (int o = 1; o < 16; o <<= 1)
                rs += __shfl_xor_sync(0xffffffffu, rs, o);
            l[i] = l[i] * alpha + rs;
#pragma unroll
            for (int j = 0; j < 8; j++) acc[i][j] *= alpha;
#pragma unroll
            for (int j = 0; j < 4; j++)
                Ps[(ty + 16 * i) * 68 + tx + 16 * j] = s[i][j];
        }
        __syncthreads();

#pragma unroll 2
        for (int j = 0; j < 64; j++) {
            float pj[4];
#pragma unroll
            for (int i = 0; i < 4; i++) pj[i] = Ps[(ty + 16 * i) * 68 + j];
#pragma unroll
            for (int c = 0; c < 8; c++) {
                float vv = Vs[j * 128 + tx + 16 * c];
#pragma unroll
                for (int i = 0; i < 4; i++) acc[i][c] = fmaf(pj[i], vv, acc[i][c]);
            }
        }
    }

#pragma unroll
    for (int i = 0; i < 4; i++) {
        float inv = 1.f / l[i];
        int orow = row0 + ty + 16 * i;
#pragma unroll
        for (int c = 0; c < 8; c++)
            out[(size_t)orow * 2048 + h * 128 + tx + 16 * c] = acc[i][c] * inv;
    }
}

// ---------------------------------------------------------------------------
// Host launcher
// ---------------------------------------------------------------------------
extern "C" void kernel_launch(void* const* d_in, const int* in_sizes, int n_in,
                              void* d_out, int out_size)
{
    (void)in_sizes; (void)n_in; (void)out_size;

    const float* x     = (const float*)d_in[0];
    const float* W_dkv = (const float*)d_in[1];
    const float* b_dkv = (const float*)d_in[2];
    const float* W_kr  = (const float*)d_in[3];
    const float* b_kr  = (const float*)d_in[4];
    const float* W_qr  = (const float*)d_in[5];
    const float* b_qr  = (const float*)d_in[6];
    const float* W_uv  = (const float*)d_in[7];
    const float* b_uv  = (const float*)d_in[8];
    const float* W_uq  = (const float*)d_in[9];
    const float* b_uq  = (const float*)d_in[10];
    const float* W_o   = (const float*)d_in[11];
    const float* b_o   = (const float*)d_in[12];
    float* out = (float*)d_out;

    float *h, *kr, *qr, *kvb, *qb, *attn;
    cudaGetSymbolAddress((void**)&h,    g_h);
    cudaGetSymbolAddress((void**)&kr,   g_kr);
    cudaGetSymbolAddress((void**)&qr,   g_qr);
    cudaGetSymbolAddress((void**)&kvb,  g_kv);
    cudaGetSymbolAddress((void**)&qb,   g_q);
    cudaGetSymbolAddress((void**)&attn, g_attn);

    const int M = MROWS;  // 4096

    // 1) h = x @ W_dkv + b_dkv            [4096,1024]
    gemm_bf16x3<<<dim3(1024 / 128, M / 128), 256>>>(x, CC, 0, W_dkv, b_dkv, h, 1024, 1024, CC);
    // 2) kr_lin = h @ W_kr + b_kr         [4096,64]
    sgemm_bias<<<dim3(64 / GBN, M / GBM), 256>>>(h, 1024, 0, W_kr, b_kr, kr, 64, M, 64, 1024);
    // 3) qr_lin = h @ W_qr + b_qr         [4096,1024]
    gemm_bf16x3<<<dim3(1024 / 128, M / 128), 256>>>(h, 1024, 0, W_qr, b_qr, qr, 1024, 1024, 1024);
    // 4) RoPE on both branches
    {
        int n1 = M * (64 / 2);
        rope_kernel<<<(n1 + 255) / 256, 256>>>(kr, M, 64);
        int n2 = M * (1024 / 2);
        rope_kernel<<<(n2 + 255) / 256, 256>>>(qr, M, 1024);
    }
    // 5) kv = cKV @ W_uv + b_uv           [4096,4096]
    gemm_bf16x3<<<dim3(4096 / 128, M / 128), 256>>>(h, 1024, 0, W_uv, b_uv, kvb, 4096, 4096, LATT);
    // 6) q = cq @ W_uq + b_uq             [4096,2048]
    gemm_bf16x3<<<dim3(2048 / 128, M / 128), 256>>>(h, 1024, LATT, W_uq, b_uq, qb, 2048, 2048, LATT);
    // 7) attention -> g_attn
    {
        size_t smem = (size_t)(64 * 196 + 64 * 196 + 64 * 128 + 64 * 68) * sizeof(float);
        cudaFuncSetAttribute(attn_flash, cudaFuncAttributeMaxDynamicSharedMemorySize, (int)smem);
        attn_flash<<<dim3(TT / 64, BB * NHH), 256, smem>>>(qb, qr, kvb, kr, attn);
    }
    // 8) out = attn @ W_o + b_o           [4096,2048]
    gemm_bf16x3<<<dim3(2048 / 128, M / 128), 256>>>(attn, 2048, 0, W_o, b_o, out, 2048, 2048, 2048);
}

// round 4
// speedup vs baseline: 10.0840x; 1.1420x over previous
#include <cuda_runtime.h>
#include <cuda_bf16.h>
#include <math.h>
#include <stdint.h>

// Problem constants
#define BB   2
#define TT   2048
#define CC   2048
#define NHH  16
#define DKK  128
#define LATT 512
#define DHRR 64
#define MROWS (BB * TT)   // 4096

typedef __nv_bfloat16 bf16;

// ---------------------------------------------------------------------------
// Scratch (static device globals -- no allocation allowed)
// ---------------------------------------------------------------------------
__device__ float g_h   [(size_t)MROWS * 1024];
__device__ float g_kr  [(size_t)MROWS * 64];
__device__ float g_qr  [(size_t)MROWS * 1024];
__device__ float g_kv  [(size_t)MROWS * 4096];
__device__ float g_q   [(size_t)MROWS * 2048];
__device__ float g_attn[(size_t)MROWS * 2048];

// bf16 K-tripled copies (3-term compensated product)
__device__ bf16 g_x2   [(size_t)MROWS * 6144];   // x    [4096, 3*2048]
__device__ bf16 g_h2   [(size_t)MROWS * 3072];   // h    [4096, 3*1024]
__device__ bf16 g_attn2[(size_t)MROWS * 6144];   // attn [4096, 3*2048]
__device__ bf16 g_wdkv2[(size_t)6144 * 1024];
__device__ bf16 g_wqr2 [(size_t)3072 * 1024];
__device__ bf16 g_wuv2 [(size_t)1536 * 4096];
__device__ bf16 g_wuq2 [(size_t)1536 * 2048];
__device__ bf16 g_wo2  [(size_t)6144 * 2048];

// ---------------------------------------------------------------------------
// PTX helpers
// ---------------------------------------------------------------------------
__device__ __forceinline__ uint32_t smem_u32(const void* p)
{ return (uint32_t)__cvta_generic_to_shared(p); }

__device__ __forceinline__ void cp16(uint32_t dst, const void* src)
{ asm volatile("cp.async.cg.shared.global [%0], [%1], 16;\n" :: "r"(dst), "l"(src)); }

__device__ __forceinline__ void cp_commit()
{ asm volatile("cp.async.commit_group;\n"); }

template <int N>
__device__ __forceinline__ void cp_wait()
{ asm volatile("cp.async.wait_group %0;\n" :: "n"(N)); }

__device__ __forceinline__ void ldm_x4(uint32_t* r, uint32_t addr)
{
    asm volatile("ldmatrix.sync.aligned.m8n8.x4.shared.b16 {%0,%1,%2,%3}, [%4];\n"
        : "=r"(r[0]), "=r"(r[1]), "=r"(r[2]), "=r"(r[3]) : "r"(addr));
}
__device__ __forceinline__ void ldm_x4t(uint32_t* r, uint32_t addr)
{
    asm volatile("ldmatrix.sync.aligned.m8n8.x4.trans.shared.b16 {%0,%1,%2,%3}, [%4];\n"
        : "=r"(r[0]), "=r"(r[1]), "=r"(r[2]), "=r"(r[3]) : "r"(addr));
}
__device__ __forceinline__ void mma_bf16(float* d, const uint32_t* a, const uint32_t* b)
{
    asm volatile(
        "mma.sync.aligned.m16n8k16.row.col.f32.bf16.bf16.f32 "
        "{%0,%1,%2,%3}, {%4,%5,%6,%7}, {%8,%9}, {%0,%1,%2,%3};\n"
        : "+f"(d[0]), "+f"(d[1]), "+f"(d[2]), "+f"(d[3])
        : "r"(a[0]), "r"(a[1]), "r"(a[2]), "r"(a[3]), "r"(b[0]), "r"(b[1]));
}

// ---------------------------------------------------------------------------
// Conversion kernels: fp32 -> K-tripled bf16
//  A-triple per element k: (hi, hi, lo)   B-triple: (hi, lo, hi)
//  => plain bf16 GEMM over K'=3K computes Ahi*Bhi + Ahi*Blo + Alo*Bhi
// ---------------------------------------------------------------------------
__global__ void convert_act(const float* __restrict__ A, int lda, int aoff,
                            int Kw, bf16* __restrict__ out)
{
    int idx = blockIdx.x * blockDim.x + threadIdx.x;
    if (idx >= MROWS * Kw) return;
    int m = idx / Kw, k = idx - m * Kw;
    float v = A[(size_t)m * lda + aoff + k];
    bf16 hi = __float2bfloat16(v);
    bf16 lo = __float2bfloat16(v - __bfloat162float(hi));
    bf16* o = out + (size_t)m * (3 * Kw) + 3 * k;
    o[0] = hi; o[1] = hi; o[2] = lo;
}

__global__ void convert_w(const float* __restrict__ W, int K, int N,
                          bf16* __restrict__ out)
{
    int idx = blockIdx.x * blockDim.x + threadIdx.x;
    if (idx >= K * N) return;
    int k = idx / N, n = idx - k * N;
    float v = W[(size_t)k * N + n];
    bf16 hi = __float2bfloat16(v);
    bf16 lo = __float2bfloat16(v - __bfloat162float(hi));
    out[(size_t)(3 * k + 0) * N + n] = hi;
    out[(size_t)(3 * k + 1) * N + n] = lo;
    out[(size_t)(3 * k + 2) * N + n] = hi;
}

// ---------------------------------------------------------------------------
// bf16 tensor-core GEMM: Y[M,N] = A[M,K'](ldk, aoff) @ W[K',N] + bias (fp32)
// 128x128x32 tile, 256 threads (8 warps 2x4, 64x32 per warp),
// cp.async double buffering, ldmatrix fragments, mma.m16n8k16.
// Requires M%128==0, N%128==0, K'%32==0.
// ---------------------------------------------------------------------------
#define AST 40    // A smem row stride (bf16): 32 + 8 pad
#define BST 136   // B smem row stride (bf16): 128 + 8 pad

__global__ __launch_bounds__(256)
void gemm_bf16tc(const bf16* __restrict__ A, int ldk, int aoff,
                 const bf16* __restrict__ W, int N, int K,
                 const float* __restrict__ bias,
                 float* __restrict__ Y, int ldy)
{
    __shared__ bf16 As[2][128 * AST];
    __shared__ bf16 Bs[2][32 * BST];

    const int tid = threadIdx.x, lane = tid & 31, wid = tid >> 5;
    const int brow = blockIdx.y * 128, bcol = blockIdx.x * 128;
    const int wm = (wid >> 2) * 64, wn = (wid & 3) * 32;

    // cp.async mapping: A 512 x 16B chunks, B 512 x 16B chunks, 2 each/thread
    const int ar0 = tid >> 2, aseg = (tid & 3) * 8;        // A rows ar0, ar0+64
    const int br0 = tid >> 4, bseg = (tid & 15) * 8;       // B rows br0, br0+16

    const bf16* Abase = A + (size_t)(brow + ar0) * ldk + aoff + aseg;
    const bf16* Wbase = W + (size_t)br0 * N + bcol + bseg;

    uint32_t sA[2], sB[2];
    sA[0] = smem_u32(&As[0][0]); sA[1] = smem_u32(&As[1][0]);
    sB[0] = smem_u32(&Bs[0][0]); sB[1] = smem_u32(&Bs[1][0]);

    const uint32_t dA0 = (uint32_t)(ar0 * AST + aseg) * 2;
    const uint32_t dA1 = (uint32_t)((ar0 + 64) * AST + aseg) * 2;
    const uint32_t dB0 = (uint32_t)(br0 * BST + bseg) * 2;
    const uint32_t dB1 = (uint32_t)((br0 + 16) * BST + bseg) * 2;

    const int nk = K / 32;

    // issue stage st loads for k-tile kt
    auto issue = [&](int st, int kt) {
        const bf16* Ap = Abase + kt * 32;
        const bf16* Wp = Wbase + (size_t)(kt * 32) * N;
        cp16(sA[st] + dA0, Ap);
        cp16(sA[st] + dA1, Ap + (size_t)64 * ldk);
        cp16(sB[st] + dB0, Wp);
        cp16(sB[st] + dB1, Wp + (size_t)16 * N);
        cp_commit();
    };

    float acc[4][4][4];
#pragma unroll
    for (int i = 0; i < 4; i++)
#pragma unroll
        for (int j = 0; j < 4; j++)
#pragma unroll
            for (int f = 0; f < 4; f++) acc[i][j][f] = 0.f;

    issue(0, 0);

    const int l16 = lane & 15, lhi = (lane >> 4) * 8;

    for (int kt = 0; kt < nk; kt++) {
        int cur = kt & 1;
        if (kt + 1 < nk) {
            issue(cur ^ 1, kt + 1);
            cp_wait<1>();
        } else {
            cp_wait<0>();
        }
        __syncthreads();

#pragma unroll
        for (int kk = 0; kk < 32; kk += 16) {
            uint32_t a[4][4], b[4][2];
#pragma unroll
            for (int i = 0; i < 4; i++) {
                uint32_t addr = sA[cur] +
                    (uint32_t)((wm + i * 16 + l16) * AST + kk + lhi) * 2;
                ldm_x4(a[i], addr);
            }
#pragma unroll
            for (int j2 = 0; j2 < 2; j2++) {
                uint32_t t[4];
                uint32_t addr = sB[cur] +
                    (uint32_t)((kk + l16) * BST + wn + j2 * 16 + lhi) * 2;
                ldm_x4t(t, addr);
                b[j2 * 2 + 0][0] = t[0]; b[j2 * 2 + 0][1] = t[1];
                b[j2 * 2 + 1][0] = t[2]; b[j2 * 2 + 1][1] = t[3];
            }
#pragma unroll
            for (int i = 0; i < 4; i++)
#pragma unroll
                for (int j = 0; j < 4; j++)
                    mma_bf16(acc[i][j], a[i], b[j]);
        }
        __syncthreads();
    }

    // epilogue: bias + fp32 store
#pragma unroll
    for (int i = 0; i < 4; i++) {
#pragma unroll
        for (int j = 0; j < 4; j++) {
            int r0 = brow + wm + i * 16 + (lane >> 2);
            int c0 = bcol + wn + j * 8 + (lane & 3) * 2;
            float b0 = bias[c0], b1 = bias[c0 + 1];
            float2 v0 = {acc[i][j][0] + b0, acc[i][j][1] + b1};
            float2 v1 = {acc[i][j][2] + b0, acc[i][j][3] + b1};
            *(float2*)&Y[(size_t)r0 * ldy + c0] = v0;
            *(float2*)&Y[(size_t)(r0 + 8) * ldy + c0] = v1;
        }
    }
}

// ---------------------------------------------------------------------------
// Small SGEMM (kept for the N=64 W_kr projection only)
// ---------------------------------------------------------------------------
#define GBM 64
#define GBN 64
#define GBK 16

__global__ __launch_bounds__(256)
void sgemm_bias(const float* __restrict__ A, int lda, int aoff,
                const float* __restrict__ W,
                const float* __restrict__ bias,
                float* __restrict__ Y, int ldy,
                int M, int N, int K)
{
    __shared__ float As[GBK][GBM];
    __shared__ float Bs[GBK][GBN];

    const int tid = threadIdx.x;
    const int brow = blockIdx.y * GBM;
    const int bcol = blockIdx.x * GBN;
    const int tr = (tid / 16) * 4;
    const int tc = (tid % 16) * 4;

    float acc[4][4];
#pragma unroll
    for (int i = 0; i < 4; i++)
#pragma unroll
        for (int j = 0; j < 4; j++) acc[i][j] = 0.f;

    for (int k0 = 0; k0 < K; k0 += GBK) {
#pragma unroll
        for (int it = 0; it < (GBM * GBK) / 256; it++) {
            int i = tid + it * 256;
            int m = i / GBK, kk = i % GBK;
            As[kk][m] = A[(size_t)(brow + m) * lda + aoff + k0 + kk];
        }
#pragma unroll
        for (int it = 0; it < (GBK * GBN) / 256; it++) {
            int i = tid + it * 256;
            int kk = i / GBN, n = i % GBN;
            Bs[kk][n] = W[(size_t)(k0 + kk) * N + bcol + n];
        }
        __syncthreads();

#pragma unroll
        for (int kk = 0; kk < GBK; kk++) {
            float a[4], b[4];
#pragma unroll
            for (int i = 0; i < 4; i++) a[i] = As[kk][tr + i];
#pragma unroll
            for (int j = 0; j < 4; j++) b[j] = Bs[kk][tc + j];
#pragma unroll
            for (int i = 0; i < 4; i++)
#pragma unroll
                for (int j = 0; j < 4; j++) acc[i][j] = fmaf(a[i], b[j], acc[i][j]);
        }
        __syncthreads();
    }

#pragma unroll
    for (int i = 0; i < 4; i++)
#pragma unroll
        for (int j = 0; j < 4; j++)
            Y[(size_t)(brow + tr + i) * ldy + bcol + tc + j] =
                acc[i][j] + bias[bcol + tc + j];
}

// ---------------------------------------------------------------------------
// Interleaved RoPE (double-precision trig; angles up to ~2048 rad)
// ---------------------------------------------------------------------------
__global__ void rope_kernel(float* __restrict__ buf, int rows, int c)
{
    const int pairs = c >> 1;
    const int idx = blockIdx.x * blockDim.x + threadIdx.x;
    if (idx >= rows * pairs) return;
    const int row = idx / pairs;
    const int i   = idx - row * pairs;
    const int t   = row & (TT - 1);

    float theta = (float)exp(-2.0 * (double)i / (double)c * log(10000.0));
    float angle = (float)(t + 1) * theta;
    double a = (double)angle;
    float cs = (float)cos(a);
    float sn = (float)sin(a);

    float* p = buf + (size_t)row * c + 2 * i;
    float x0 = p[0], x1 = p[1];
    p[0] = x0 * cs - x1 * sn;
    p[1] = x1 * cs + x0 * sn;
}

// ---------------------------------------------------------------------------
// Flash attention: 64 queries x 64 keys per tile, 256 threads.
// ---------------------------------------------------------------------------
__global__ __launch_bounds__(256)
void attn_flash(const float* __restrict__ q, const float* __restrict__ qr,
                const float* __restrict__ kv, const float* __restrict__ kr,
                float* __restrict__ out)
{
    extern __shared__ float sm[];
    float* Qs = sm;                  // [64][196]
    float* Ks = Qs + 64 * 196;       // [64][196]
    float* Vs = Ks + 64 * 196;       // [64][128]
    float* Ps = Vs + 64 * 128;       // [64][68]

    const int bh = blockIdx.y;
    const int b = bh >> 4, h = bh & 15;
    const int qb = gridDim.x - 1 - blockIdx.x;   // largest blocks first
    const int tid = threadIdx.x;
    const int ty = tid >> 4, tx = tid & 15;
    const int row0 = b * TT + qb * 64;
    const size_t kbase = (size_t)b * TT;
    const float scale = 0.08838834764831845f;    // 1/sqrt(128)

    for (int idx = tid; idx < 64 * 48; idx += 256) {
        int qi = idx / 48, d4 = (idx % 48) * 4;
        float4 v;
        if (d4 < 128)
            v = *(const float4*)&q[(size_t)(row0 + qi) * 2048 + h * 128 + d4];
        else
            v = *(const float4*)&qr[(size_t)(row0 + qi) * 1024 + h * 64 + (d4 - 128)];
        v.x *= scale; v.y *= scale; v.z *= scale; v.w *= scale;
        *(float4*)&Qs[qi * 196 + d4] = v;
    }

    float m[4], l[4], acc[4][8];
#pragma unroll
    for (int i = 0; i < 4; i++) {
        m[i] = -3.0e38f; l[i] = 0.f;
#pragma unroll
        for (int j = 0; j < 8; j++) acc[i][j] = 0.f;
    }

    const int ntiles = qb + 1;
    for (int t = 0; t < ntiles; t++) {
        const int j0 = t * 64;
        __syncthreads();
        for (int idx = tid; idx < 64 * 48; idx += 256) {
            int j = idx / 48, d4 = (idx % 48) * 4;
            float4 v;
            if (d4 < 128)
                v = *(const float4*)&kv[(kbase + j0 + j) * 4096 + h * 128 + d4];
            else
                v = *(const float4*)&kr[(kbase + j0 + j) * 64 + (d4 - 128)];
            *(float4*)&Ks[j * 196 + d4] = v;
        }
        for (int idx = tid; idx < 64 * 32; idx += 256) {
            int j = idx / 32, d4 = (idx % 32) * 4;
            *(float4*)&Vs[j * 128 + d4] =
                *(const float4*)&kv[(kbase + j0 + j) * 4096 + 2048 + h * 128 + d4];
        }
        __syncthreads();

        float s[4][4];
#pragma unroll
        for (int i = 0; i < 4; i++)
#pragma unroll
            for (int j = 0; j < 4; j++) s[i][j] = 0.f;

        for (int d4 = 0; d4 < 192; d4 += 4) {
            float4 qv[4], kk[4];
#pragma unroll
            for (int i = 0; i < 4; i++) qv[i] = *(float4*)&Qs[(ty + 16 * i) * 196 + d4];
#pragma unroll
            for (int j = 0; j < 4; j++) kk[j] = *(float4*)&Ks[(tx + 16 * j) * 196 + d4];
#pragma unroll
            for (int i = 0; i < 4; i++)
#pragma unroll
                for (int j = 0; j < 4; j++) {
                    s[i][j] = fmaf(qv[i].x, kk[j].x, s[i][j]);
                    s[i][j] = fmaf(qv[i].y, kk[j].y, s[i][j]);
                    s[i][j] = fmaf(qv[i].z, kk[j].z, s[i][j]);
                    s[i][j] = fmaf(qv[i].w, kk[j].w, s[i][j]);
                }
        }

        if (t == ntiles - 1) {
#pragma unroll
            for (int i = 0; i < 4; i++) {
                int qrow = qb * 64 + ty + 16 * i;
#pragma unroll
                for (int j = 0; j < 4; j++)
                    if (j0 + tx + 16 * j > qrow) s[i][j] = -1.0e30f;
            }
        }

#pragma unroll
        for (int i = 0; i < 4; i++) {
            float mr = fmaxf(fmaxf(s[i][0], s[i][1]), fmaxf(s[i][2], s[i][3]));
#pragma unroll
            for (int o = 1; o < 16; o <<= 1)
                mr = fmaxf(mr, __shfl_xor_sync(0xffffffffu, mr, o));
            float mn = fmaxf(m[i], mr);
            float alpha = __expf(m[i] - mn);
            m[i] = mn;
            float rs = 0.f;
#pragma unroll
            for (int j = 0; j < 4; j++) {
                float p = __expf(s[i][j] - mn);
                s[i][j] = p;
                rs += p;
            }
#pragma unroll
            for (int o = 1; o < 16; o <<= 1)
                rs += __shfl_xor_sync(0xffffffffu, rs, o);
            l[i] = l[i] * alpha + rs;
#pragma unroll
            for (int j = 0; j < 8; j++) acc[i][j] *= alpha;
#pragma unroll
            for (int j = 0; j < 4; j++)
                Ps[(ty + 16 * i) * 68 + tx + 16 * j] = s[i][j];
        }
        __syncthreads();

#pragma unroll 2
        for (int j = 0; j < 64; j++) {
            float pj[4];
#pragma unroll
            for (int i = 0; i < 4; i++) pj[i] = Ps[(ty + 16 * i) * 68 + j];
#pragma unroll
            for (int c = 0; c < 8; c++) {
                float vv = Vs[j * 128 + tx + 16 * c];
#pragma unroll
                for (int i = 0; i < 4; i++) acc[i][c] = fmaf(pj[i], vv, acc[i][c]);
            }
        }
    }

#pragma unroll
    for (int i = 0; i < 4; i++) {
        float inv = 1.f / l[i];
        int orow = row0 + ty + 16 * i;
#pragma unroll
        for (int c = 0; c < 8; c++)
            out[(size_t)orow * 2048 + h * 128 + tx + 16 * c] = acc[i][c] * inv;
    }
}

// ---------------------------------------------------------------------------
// Host launcher
// ---------------------------------------------------------------------------
extern "C" void kernel_launch(void* const* d_in, const int* in_sizes, int n_in,
                              void* d_out, int out_size)
{
    (void)in_sizes; (void)n_in; (void)out_size;

    const float* x     = (const float*)d_in[0];
    const float* W_dkv = (const float*)d_in[1];
    const float* b_dkv = (const float*)d_in[2];
    const float* W_kr  = (const float*)d_in[3];
    const float* b_kr  = (const float*)d_in[4];
    const float* W_qr  = (const float*)d_in[5];
    const float* b_qr  = (const float*)d_in[6];
    const float* W_uv  = (const float*)d_in[7];
    const float* b_uv  = (const float*)d_in[8];
    const float* W_uq  = (const float*)d_in[9];
    const float* b_uq  = (const float*)d_in[10];
    const float* W_o   = (const float*)d_in[11];
    const float* b_o   = (const float*)d_in[12];
    float* out = (float*)d_out;

    float *h, *kr, *qr, *kvb, *qb, *attn;
    bf16 *x2, *h2, *attn2, *wdkv2, *wqr2, *wuv2, *wuq2, *wo2;
    cudaGetSymbolAddress((void**)&h,    g_h);
    cudaGetSymbolAddress((void**)&kr,   g_kr);
    cudaGetSymbolAddress((void**)&qr,   g_qr);
    cudaGetSymbolAddress((void**)&kvb,  g_kv);
    cudaGetSymbolAddress((void**)&qb,   g_q);
    cudaGetSymbolAddress((void**)&attn, g_attn);
    cudaGetSymbolAddress((void**)&x2,    g_x2);
    cudaGetSymbolAddress((void**)&h2,    g_h2);
    cudaGetSymbolAddress((void**)&attn2, g_attn2);
    cudaGetSymbolAddress((void**)&wdkv2, g_wdkv2);
    cudaGetSymbolAddress((void**)&wqr2,  g_wqr2);
    cudaGetSymbolAddress((void**)&wuv2,  g_wuv2);
    cudaGetSymbolAddress((void**)&wuq2,  g_wuq2);
    cudaGetSymbolAddress((void**)&wo2,   g_wo2);

    const int M = MROWS;  // 4096

    // weight conversions (deterministic each launch)
    convert_w<<<(2048 * 1024 + 255) / 256, 256>>>(W_dkv, 2048, 1024, wdkv2);
    convert_w<<<(1024 * 1024 + 255) / 256, 256>>>(W_qr, 1024, 1024, wqr2);
    convert_w<<<(512 * 4096 + 255) / 256, 256>>>(W_uv, 512, 4096, wuv2);
    convert_w<<<(512 * 2048 + 255) / 256, 256>>>(W_uq, 512, 2048, wuq2);
    convert_w<<<(2048 * 2048 + 255) / 256, 256>>>(W_o, 2048, 2048, wo2);

    // x -> x2
    convert_act<<<(M * 2048 + 255) / 256, 256>>>(x, 2048, 0, 2048, x2);

    // 1) h = x @ W_dkv + b_dkv            [4096,1024]
    gemm_bf16tc<<<dim3(1024 / 128, M / 128), 256>>>(x2, 6144, 0, wdkv2, 1024, 6144, b_dkv, h, 1024);

    // 2) kr_lin = h @ W_kr + b_kr         [4096,64] (fp32, tiny)
    sgemm_bias<<<dim3(64 / GBN, M / GBM), 256>>>(h, 1024, 0, W_kr, b_kr, kr, 64, M, 64, 1024);

    // h -> h2
    convert_act<<<(M * 1024 + 255) / 256, 256>>>(h, 1024, 0, 1024, h2);

    // 3) qr_lin = h @ W_qr + b_qr         [4096,1024]
    gemm_bf16tc<<<dim3(1024 / 128, M / 128), 256>>>(h2, 3072, 0, wqr2, 1024, 3072, b_qr, qr, 1024);

    // 4) RoPE on both branches
    {
        int n1 = M * (64 / 2);
        rope_kernel<<<(n1 + 255) / 256, 256>>>(kr, M, 64);
        int n2 = M * (1024 / 2);
        rope_kernel<<<(n2 + 255) / 256, 256>>>(qr, M, 1024);
    }

    // 5) kv = cKV @ W_uv + b_uv           [4096,4096]   (h2 cols 0..1535)
    gemm_bf16tc<<<dim3(4096 / 128, M / 128), 256>>>(h2, 3072, 0, wuv2, 4096, 1536, b_uv, kvb, 4096);
    // 6) q = cq @ W_uq + b_uq             [4096,2048]   (h2 cols 1536..)
    gemm_bf16tc<<<dim3(2048 / 128, M / 128), 256>>>(h2, 3072, 1536, wuq2, 2048, 1536, b_uq, qb, 2048);

    // 7) attention -> g_attn
    {
        size_t smem = (size_t)(64 * 196 + 64 * 196 + 64 * 128 + 64 * 68) * sizeof(float);
        cudaFuncSetAttribute(attn_flash, cudaFuncAttributeMaxDynamicSharedMemorySize, (int)smem);
        attn_flash<<<dim3(TT / 64, BB * NHH), 256, smem>>>(qb, qr, kvb, kr, attn);
    }

    // attn -> attn2
    convert_act<<<(M * 2048 + 255) / 256, 256>>>(attn, 2048, 0, 2048, attn2);

    // 8) out = attn @ W_o + b_o           [4096,2048]
    gemm_bf16tc<<<dim3(2048 / 128, M / 128), 256>>>(attn2, 6144, 0, wo2, 2048, 6144, b_o, out, 2048);
}